// round 3
// baseline (speedup 1.0000x reference)
#include <cuda_runtime.h>
#include <math.h>

#define NN      2304                    // 48*48
#define BB      2
#define CF      32
#define PCH     3
#define TILE    128
#define NT      (NN / TILE)             // 18
#define TPAIRS  (NT * (NT + 1) / 2)     // 171
#define NBLOCKS (BB * TPAIRS)           // 342
#define KP      2.8853900817779268f     // 4 / ln(4)
#define CEXP    -5.770780163555851f     // -4 * log2(e)
#define SQ2     1.4142135623730951f

// ---- scratch (no allocations allowed) ----
__device__ float4 g_st4[BB * NN];       // (mu, var, 0.25/var, -)
__device__ float4 g_pa4[BB * NN];       // (sqrt2*pE1, sqrt2*pE2, sqrt2*pE3, q1^2)
__device__ float2 g_pb2[BB * NN];       // (q2^2, q3^2)
__device__ float  g_inorm[BB * NN];     // rsqrt(||f||^2)
__device__ float  g_partial[NBLOCKS];
__device__ int    g_count = 0;

typedef unsigned long long u64;

// ---- packed f32x2 helpers (sm_103a) ----
#define FMA2(d, a, b, c) asm("fma.rn.f32x2 %0, %1, %2, %3;" \
    : "=l"(d) : "l"(a), "l"(b), "l"(c))
#define MUL2(d, a, b) asm("mul.rn.f32x2 %0, %1, %2;" \
    : "=l"(d) : "l"(a), "l"(b))
#define ADD2(d, a, b) asm("add.rn.f32x2 %0, %1, %2;" \
    : "=l"(d) : "l"(a), "l"(b))
#define PACK2(d, x) asm("mov.b64 %0, {%1, %1};" : "=l"(d) : "f"(x))
#define UNPACK2(lo, hi, v) asm("mov.b64 {%0, %1}, %2;" \
    : "=f"(lo), "=f"(hi) : "l"(v))

__device__ __forceinline__ float ex2f(float x) {
    float r; asm("ex2.approx.f32 %0, %1;" : "=f"(r) : "f"(x)); return r;
}
__device__ __forceinline__ float rcpf(float x) {
    float r; asm("rcp.approx.f32 %0, %1;" : "=f"(r) : "f"(x)); return r;
}

// ============================================================
// Kernel A: per-node stats + softmax-derived quantities
// ============================================================
__global__ void precompute_kernel(const float* __restrict__ f,
                                  const float* __restrict__ p) {
    int idx = blockIdx.x * 64 + threadIdx.x;
    if (idx >= BB * NN) return;
    int b = idx / NN;
    int n = idx - b * NN;

    const float* fb = f + (size_t)b * CF * NN + n;
    float s = 0.0f, ss = 0.0f;
#pragma unroll
    for (int c = 0; c < CF; c++) {
        float v = fb[c * NN];
        s += v;
        ss = fmaf(v, v, ss);
    }
    float mu  = s * (1.0f / CF);
    float var = (ss - s * mu) * (1.0f / (CF - 1));
    g_st4[idx]   = make_float4(mu, var, 0.25f / var, 0.0f);
    g_inorm[idx] = rsqrtf(ss);

    const float* pp = p + (size_t)b * 4 * NN + n;
    float e0 = __expf(pp[0]);
    float e1 = __expf(pp[NN]);
    float e2 = __expf(pp[2 * NN]);
    float e3 = __expf(pp[3 * NN]);
    float inv = __fdividef(1.0f, e0 + e1 + e2 + e3);
    float q1 = e1 * inv, q2 = e2 * inv, q3 = e3 * inv;
    float E1 = fmaf(KP * q1, __logf(q1), 1.0f);
    float E2 = fmaf(KP * q2, __logf(q2), 1.0f);
    float E3 = fmaf(KP * q3, __logf(q3), 1.0f);
    // sqrt(2) folded in so pEi*pEj carries the factor 2 of A
    g_pa4[idx] = make_float4(SQ2 * q1 * E1, SQ2 * q2 * E2, SQ2 * q3 * E3, q1 * q1);
    g_pb2[idx] = make_float2(q2 * q2, q3 * q3);
}

// ============================================================
// Kernel B: pairwise tile kernel + fused final reduction
//   512 threads, 4i x 8j micro-tile, f32x2 throughout
// ============================================================
__global__ void __launch_bounds__(512, 2) pair_kernel(const float* __restrict__ f,
                                                      float* __restrict__ out) {
    int blk = blockIdx.x;
    int b = blk / TPAIRS;
    int r = blk - b * TPAIRS;
    int ti = 0;
    while (r >= NT - ti) { r -= NT - ti; ti++; }
    int tj = ti + r;

    __shared__ __align__(16) float  fi_s[CF][TILE];
    __shared__ __align__(16) float  fj_s[CF][TILE];
    // j-side SoA (plain):   0:-mu  1:v  2:z  3..5:pE  6..8:q^2
    __shared__ __align__(16) float  js[9][TILE];
    // i-side SoA (lane-duplicated float2): same order, mu NOT negated
    __shared__ __align__(16) float2 id[9][TILE];
    __shared__ float red_s[16];
    __shared__ int   is_last;

    int t    = threadIdx.x;
    int lane = t & 31, warp = t >> 5;
    int i0 = ti * TILE, j0 = tj * TILE;
    const float* fb = f + (size_t)b * CF * NN;

    // ---- load f tiles (normalized) ----
    {
        int e  = t & (TILE - 1);
        int c0 = t >> 7;                       // 0..3
        float invi = g_inorm[b * NN + i0 + e];
        float invj = g_inorm[b * NN + j0 + e];
#pragma unroll
        for (int k = 0; k < CF / 4; k++) {
            int c = c0 + 4 * k;
            fi_s[c][e] = fb[c * NN + i0 + e] * invi;
            fj_s[c][e] = fb[c * NN + j0 + e] * invj;
        }
    }
    // ---- build stat SoA ----
    if (t < TILE) {
        int e = t;
        float4 si = g_st4[b * NN + i0 + e];
        float4 pi = g_pa4[b * NN + i0 + e];
        float2 qi = g_pb2[b * NN + i0 + e];
        id[0][e] = make_float2(si.x, si.x);
        id[1][e] = make_float2(si.y, si.y);
        id[2][e] = make_float2(si.z, si.z);
        id[3][e] = make_float2(pi.x, pi.x);
        id[4][e] = make_float2(pi.y, pi.y);
        id[5][e] = make_float2(pi.z, pi.z);
        id[6][e] = make_float2(pi.w, pi.w);
        id[7][e] = make_float2(qi.x, qi.x);
        id[8][e] = make_float2(qi.y, qi.y);
        float4 sj = g_st4[b * NN + j0 + e];
        float4 pj = g_pa4[b * NN + j0 + e];
        float2 qj = g_pb2[b * NN + j0 + e];
        js[0][e] = -sj.x;
        js[1][e] = sj.y;
        js[2][e] = sj.z;
        js[3][e] = pj.x;
        js[4][e] = pj.y;
        js[5][e] = pj.z;
        js[6][e] = pj.w;
        js[7][e] = qj.x;
        js[8][e] = qj.y;
    }
    __syncthreads();

    int tx = t & 15, ty = t >> 4;     // ty 0..31
    int jx = tx * 8, iy = ty * 4;

    // ---- gram: acc[ii][jp] packs j = jx+2jp, jx+2jp+1 ----
    u64 acc[4][4];
#pragma unroll
    for (int a = 0; a < 4; a++)
#pragma unroll
        for (int c = 0; c < 4; c++) acc[a][c] = 0ull;

#pragma unroll 8
    for (int c = 0; c < CF; c++) {
        float4 av = *(const float4*)&fi_s[c][iy];
        ulonglong2 b0 = *(const ulonglong2*)&fj_s[c][jx];
        ulonglong2 b1 = *(const ulonglong2*)&fj_s[c][jx + 4];
        float aa[4] = {av.x, av.y, av.z, av.w};
#pragma unroll
        for (int ii = 0; ii < 4; ii++) {
            u64 a2;
            PACK2(a2, aa[ii]);
            FMA2(acc[ii][0], a2, b0.x, acc[ii][0]);
            FMA2(acc[ii][1], a2, b0.y, acc[ii][1]);
            FMA2(acc[ii][2], a2, b1.x, acc[ii][2]);
            FMA2(acc[ii][3], a2, b1.y, acc[ii][3]);
        }
    }

    // ---- packed constants ----
    u64 C13, CM23, CHALF, CEXP2;
    PACK2(C13,   (1.0f / 3.0f));
    PACK2(CM23, (-2.0f / 3.0f));
    PACK2(CHALF, 0.5f);
    PACK2(CEXP2, CEXP);

    float part = 0.0f;
#pragma unroll
    for (int ii = 0; ii < 4; ii++) {
        int i = iy + ii;
        u64 mui = *(const u64*)&id[0][i];
        u64 vi  = *(const u64*)&id[1][i];
        u64 zi  = *(const u64*)&id[2][i];
        u64 ei1 = *(const u64*)&id[3][i];
        u64 ei2 = *(const u64*)&id[4][i];
        u64 ei3 = *(const u64*)&id[5][i];
        u64 si1 = *(const u64*)&id[6][i];
        u64 si2 = *(const u64*)&id[7][i];
        u64 si3 = *(const u64*)&id[8][i];
#pragma unroll
        for (int jp = 0; jp < 4; jp++) {
            int j = jx + 2 * jp;
            u64 nmuj = *(const u64*)&js[0][j];
            u64 vj   = *(const u64*)&js[1][j];
            u64 zj   = *(const u64*)&js[2][j];

            u64 dmu, a2, tt, zs, kl, d, ds, e2;
            ADD2(dmu, mui, nmuj);
            MUL2(a2, dmu, dmu);
            MUL2(tt, vj, zi);
            FMA2(tt, vi, zj, tt);
            ADD2(zs, zi, zj);
            FMA2(kl, a2, zs, tt);
            FMA2(d, kl, C13, CHALF);
            FMA2(d, acc[ii][jp], CM23, d);
            MUL2(ds, d, d);
            MUL2(e2, ds, CEXP2);
            float e0, e1;
            UNPACK2(e0, e1, e2);
            float w0 = ex2f(e0), w1 = ex2f(e1);

            u64 ej1 = *(const u64*)&js[3][j];
            u64 ej2 = *(const u64*)&js[4][j];
            u64 ej3 = *(const u64*)&js[5][j];
            u64 sj1 = *(const u64*)&js[6][j];
            u64 sj2 = *(const u64*)&js[7][j];
            u64 sj3 = *(const u64*)&js[8][j];

            u64 n1, n2, n3, d1, d2, d3, t23, t13, e12, den, num;
            MUL2(n1, ei1, ej1);
            MUL2(n2, ei2, ej2);
            MUL2(n3, ei3, ej3);
            ADD2(d1, si1, sj1);
            ADD2(d2, si2, sj2);
            ADD2(d3, si3, sj3);
            MUL2(t23, d2, d3);
            MUL2(t13, d1, d3);
            MUL2(e12, d1, d2);
            MUL2(den, e12, d3);
            MUL2(num, n1, t23);
            FMA2(num, n2, t13, num);
            FMA2(num, n3, e12, num);
            float num0, num1, den0, den1;
            UNPACK2(num0, num1, num);
            UNPACK2(den0, den1, den);
            part = fmaf(w0 * num0, rcpf(den0), part);
            part = fmaf(w1 * num1, rcpf(den1), part);
        }
    }

    if (ti != tj) part += part;           // symmetry: off-diag tiles count x2

    // ---- block reduction ----
#pragma unroll
    for (int o = 16; o; o >>= 1) part += __shfl_xor_sync(0xffffffffu, part, o);
    if (lane == 0) red_s[warp] = part;
    __syncthreads();

    if (t == 0) {
        float s = 0.0f;
#pragma unroll
        for (int w = 0; w < 16; w++) s += red_s[w];
        g_partial[blk] = s;
        __threadfence();
        is_last = (atomicAdd(&g_count, 1) == NBLOCKS - 1);
    }
    __syncthreads();

    // ---- last block: deterministic final reduction ----
    if (is_last) {
        __shared__ double dred[16];
        double s = 0.0;
        for (int i = t; i < NBLOCKS; i += 512)
            s += (double)__ldcg(&g_partial[i]);
#pragma unroll
        for (int o = 16; o; o >>= 1)
            s += __longlong_as_double(
                 __shfl_xor_sync(0xffffffffu, __double_as_longlong(s), o));
        if (lane == 0) dred[warp] = s;
        __syncthreads();
        if (t == 0) {
            double total = 0.0;
#pragma unroll
            for (int w = 0; w < 16; w++) total += dred[w];
            double score = total / ((double)BB * PCH * NN);
            out[0] = (float)(1.0 - score / (double)NN);
            g_count = 0;                   // reset for next graph replay
        }
    }
}

extern "C" void kernel_launch(void* const* d_in, const int* in_sizes, int n_in,
                              void* d_out, int out_size) {
    const float* f = (const float*)d_in[0];
    const float* p = (const float*)d_in[1];
    precompute_kernel<<<(BB * NN + 63) / 64, 64>>>(f, p);
    pair_kernel<<<NBLOCKS, 512>>>(f, (float*)d_out);
}

// round 4
// speedup vs baseline: 2.0820x; 2.0820x over previous
#include <cuda_runtime.h>
#include <math.h>

#define NN      2304                    // 48*48
#define BB      2
#define CF      32
#define PCH     3
#define TILE    64
#define NT      (NN / TILE)             // 36
#define TPAIRS  (NT * (NT + 1) / 2)     // 666
#define NBLOCKS (BB * TPAIRS)           // 1332
#define KP      2.8853900817779268f     // 4 / ln(4)
#define CEXP    -5.770780163555851f     // -4 * log2(e)
#define SQ2     1.4142135623730951f

// ---- scratch (no allocations allowed) ----
__device__ float4 g_st4[BB * NN];       // (mu, var, 0.25/var, -)
__device__ float4 g_pa4[BB * NN];       // (sqrt2*pE1..3, q1^2)
__device__ float2 g_pb2[BB * NN];       // (q2^2, q3^2)
__device__ float  g_inorm[BB * NN];     // rsqrt(||f||^2)
__device__ float  g_partial[NBLOCKS];
__device__ int    g_count = 0;

typedef unsigned long long u64;

// ---- packed f32x2 helpers (sm_103a) ----
#define FMA2(d, a, b, c) asm("fma.rn.f32x2 %0, %1, %2, %3;" \
    : "=l"(d) : "l"(a), "l"(b), "l"(c))
#define MUL2(d, a, b) asm("mul.rn.f32x2 %0, %1, %2;" \
    : "=l"(d) : "l"(a), "l"(b))
#define ADD2(d, a, b) asm("add.rn.f32x2 %0, %1, %2;" \
    : "=l"(d) : "l"(a), "l"(b))
#define PACK2(d, x) asm("mov.b64 %0, {%1, %1};" : "=l"(d) : "f"(x))
#define UNPACK2(lo, hi, v) asm("mov.b64 {%0, %1}, %2;" \
    : "=f"(lo), "=f"(hi) : "l"(v))

__device__ __forceinline__ float ex2f(float x) {
    float r; asm("ex2.approx.f32 %0, %1;" : "=f"(r) : "f"(x)); return r;
}
__device__ __forceinline__ float rcpf(float x) {
    float r; asm("rcp.approx.f32 %0, %1;" : "=f"(r) : "f"(x)); return r;
}

// ============================================================
// Kernel A: per-node stats + softmax-derived quantities
// ============================================================
__global__ void precompute_kernel(const float* __restrict__ f,
                                  const float* __restrict__ p) {
    int idx = blockIdx.x * 64 + threadIdx.x;
    if (idx >= BB * NN) return;
    int b = idx / NN;
    int n = idx - b * NN;

    const float* fb = f + (size_t)b * CF * NN + n;
    float s = 0.0f, ss = 0.0f;
#pragma unroll
    for (int c = 0; c < CF; c++) {
        float v = fb[c * NN];
        s += v;
        ss = fmaf(v, v, ss);
    }
    float mu  = s * (1.0f / CF);
    float var = (ss - s * mu) * (1.0f / (CF - 1));
    g_st4[idx]   = make_float4(mu, var, 0.25f / var, 0.0f);
    g_inorm[idx] = rsqrtf(ss);

    const float* pp = p + (size_t)b * 4 * NN + n;
    float e0 = __expf(pp[0]);
    float e1 = __expf(pp[NN]);
    float e2 = __expf(pp[2 * NN]);
    float e3 = __expf(pp[3 * NN]);
    float inv = __fdividef(1.0f, e0 + e1 + e2 + e3);
    float q1 = e1 * inv, q2 = e2 * inv, q3 = e3 * inv;
    float E1 = fmaf(KP * q1, __logf(q1), 1.0f);
    float E2 = fmaf(KP * q2, __logf(q2), 1.0f);
    float E3 = fmaf(KP * q3, __logf(q3), 1.0f);
    // sqrt(2) folded so pEi*pEj carries the factor 2 of A
    g_pa4[idx] = make_float4(SQ2 * q1 * E1, SQ2 * q2 * E2, SQ2 * q3 * E3, q1 * q1);
    g_pb2[idx] = make_float2(q2 * q2, q3 * q3);
}

// ============================================================
// Kernel B: 64x64 tile pairs, 256 thr, 4i x 4j micro-tile,
//           f32x2 gram (dup-smem, no PACK) + f32x2 epilogue
// ============================================================
__global__ void __launch_bounds__(256, 3) pair_kernel(const float* __restrict__ f,
                                                      float* __restrict__ out) {
    int blk = blockIdx.x;
    int b = blk / TPAIRS;
    int r = blk - b * TPAIRS;
    int ti = 0;
    while (r >= NT - ti) { r -= NT - ti; ti++; }
    int tj = ti + r;

    __shared__ __align__(16) float fi_d[CF][2 * TILE];  // i values duplicated
    __shared__ __align__(16) float fj_s[CF][TILE];
    // i-side SoA, duplicated: 0:mu 1:v 2:z 3..5:pE 6..8:q^2
    __shared__ __align__(16) float id_d[9][2 * TILE];
    // j-side SoA, plain:      0:-mu 1:v 2:z 3..5:pE 6..8:q^2
    __shared__ __align__(16) float js_s[9][TILE];
    __shared__ float red_s[8];
    __shared__ int   is_last;

    int t    = threadIdx.x;
    int lane = t & 31, warp = t >> 5;
    int i0 = ti * TILE, j0 = tj * TILE;
    const float* fb = f + (size_t)b * CF * NN;

    // ---- load f tiles (normalized); each thread owns column e = t&63 ----
    {
        int e  = t & (TILE - 1);
        int c0 = t >> 6;                      // 0..3
        float invi = g_inorm[b * NN + i0 + e];
        float invj = g_inorm[b * NN + j0 + e];
#pragma unroll
        for (int k = 0; k < CF / 4; k++) {
            int c = c0 + 4 * k;
            float vi = fb[c * NN + i0 + e] * invi;
            float vj = fb[c * NN + j0 + e] * invj;
            *(float2*)&fi_d[c][2 * e] = make_float2(vi, vi);
            fj_s[c][e] = vj;
        }
    }
    // ---- stat SoA ----
    if (t < TILE) {
        int e = t;
        float4 si = g_st4[b * NN + i0 + e];
        float4 pi = g_pa4[b * NN + i0 + e];
        float2 qi = g_pb2[b * NN + i0 + e];
        *(float2*)&id_d[0][2 * e] = make_float2(si.x, si.x);
        *(float2*)&id_d[1][2 * e] = make_float2(si.y, si.y);
        *(float2*)&id_d[2][2 * e] = make_float2(si.z, si.z);
        *(float2*)&id_d[3][2 * e] = make_float2(pi.x, pi.x);
        *(float2*)&id_d[4][2 * e] = make_float2(pi.y, pi.y);
        *(float2*)&id_d[5][2 * e] = make_float2(pi.z, pi.z);
        *(float2*)&id_d[6][2 * e] = make_float2(pi.w, pi.w);
        *(float2*)&id_d[7][2 * e] = make_float2(qi.x, qi.x);
        *(float2*)&id_d[8][2 * e] = make_float2(qi.y, qi.y);
        float4 sj = g_st4[b * NN + j0 + e];
        float4 pj = g_pa4[b * NN + j0 + e];
        float2 qj = g_pb2[b * NN + j0 + e];
        js_s[0][e] = -sj.x;
        js_s[1][e] = sj.y;
        js_s[2][e] = sj.z;
        js_s[3][e] = pj.x;
        js_s[4][e] = pj.y;
        js_s[5][e] = pj.z;
        js_s[6][e] = pj.w;
        js_s[7][e] = qj.x;
        js_s[8][e] = qj.y;
    }
    __syncthreads();

    int tx = t & 15, ty = t >> 4;      // 16x16 threads, 4i x 4j each
    int jx = tx * 4, iy = ty * 4;

    // ---- gram: acc[ii][jp] packs (j=jx+2jp, jx+2jp+1) ----
    u64 acc[4][2];
#pragma unroll
    for (int a = 0; a < 4; a++) { acc[a][0] = 0ull; acc[a][1] = 0ull; }

#pragma unroll 8
    for (int c = 0; c < CF; c++) {
        ulonglong2 a01 = *(const ulonglong2*)&fi_d[c][2 * iy];      // (a0,a0),(a1,a1)
        ulonglong2 a23 = *(const ulonglong2*)&fi_d[c][2 * iy + 4];  // (a2,a2),(a3,a3)
        ulonglong2 bb  = *(const ulonglong2*)&fj_s[c][jx];          // (b0,b1),(b2,b3)
        FMA2(acc[0][0], a01.x, bb.x, acc[0][0]);
        FMA2(acc[0][1], a01.x, bb.y, acc[0][1]);
        FMA2(acc[1][0], a01.y, bb.x, acc[1][0]);
        FMA2(acc[1][1], a01.y, bb.y, acc[1][1]);
        FMA2(acc[2][0], a23.x, bb.x, acc[2][0]);
        FMA2(acc[2][1], a23.x, bb.y, acc[2][1]);
        FMA2(acc[3][0], a23.y, bb.x, acc[3][0]);
        FMA2(acc[3][1], a23.y, bb.y, acc[3][1]);
    }

    // ---- packed constants ----
    u64 C13, CM23, CHALF, CEXP2;
    PACK2(C13,   (1.0f / 3.0f));
    PACK2(CM23, (-2.0f / 3.0f));
    PACK2(CHALF, 0.5f);
    PACK2(CEXP2, CEXP);

    float part = 0.0f;
#pragma unroll
    for (int ii = 0; ii < 4; ii++) {
        int i2 = 2 * (iy + ii);
        u64 mui = *(const u64*)&id_d[0][i2];
        u64 vi  = *(const u64*)&id_d[1][i2];
        u64 zi  = *(const u64*)&id_d[2][i2];
#pragma unroll
        for (int jp = 0; jp < 2; jp++) {
            int j = jx + 2 * jp;
            // KL / dist / w
            u64 dmu, dmu2, tt, zs, d, ds, e2;
            ADD2(dmu, mui, *(const u64*)&js_s[0][j]);
            MUL2(dmu2, dmu, dmu);
            MUL2(tt, *(const u64*)&js_s[1][j], zi);
            FMA2(tt, vi, *(const u64*)&js_s[2][j], tt);
            ADD2(zs, zi, *(const u64*)&js_s[2][j]);
            FMA2(tt, dmu2, zs, tt);
            FMA2(d, tt, C13, CHALF);
            FMA2(d, acc[ii][jp], CM23, d);
            MUL2(ds, d, d);
            MUL2(e2, ds, CEXP2);
            float eg0, eg1;
            UNPACK2(eg0, eg1, e2);
            float w0 = ex2f(eg0), w1 = ex2f(eg1);
            // gs with common denominator
            u64 n1, n2, n3, d1, d2, d3, t23, e12, den, num;
            MUL2(n1, *(const u64*)&id_d[3][i2], *(const u64*)&js_s[3][j]);
            MUL2(n2, *(const u64*)&id_d[4][i2], *(const u64*)&js_s[4][j]);
            MUL2(n3, *(const u64*)&id_d[5][i2], *(const u64*)&js_s[5][j]);
            ADD2(d1, *(const u64*)&id_d[6][i2], *(const u64*)&js_s[6][j]);
            ADD2(d2, *(const u64*)&id_d[7][i2], *(const u64*)&js_s[7][j]);
            ADD2(d3, *(const u64*)&id_d[8][i2], *(const u64*)&js_s[8][j]);
            MUL2(t23, d2, d3);
            MUL2(e12, d1, d2);
            MUL2(den, e12, d3);
            MUL2(num, n1, t23);
            MUL2(t23, d1, d3);
            FMA2(num, n2, t23, num);
            FMA2(num, n3, e12, num);
            float num0, num1, den0, den1;
            UNPACK2(num0, num1, num);
            UNPACK2(den0, den1, den);
            part = fmaf(w0 * num0, rcpf(den0), part);
            part = fmaf(w1 * num1, rcpf(den1), part);
        }
    }

    if (ti != tj) part += part;        // off-diagonal tile pairs count twice

    // ---- block reduction ----
#pragma unroll
    for (int o = 16; o; o >>= 1) part += __shfl_xor_sync(0xffffffffu, part, o);
    if (lane == 0) red_s[warp] = part;
    __syncthreads();

    if (t == 0) {
        float s = 0.0f;
#pragma unroll
        for (int w = 0; w < 8; w++) s += red_s[w];
        g_partial[blk] = s;
        __threadfence();
        is_last = (atomicAdd(&g_count, 1) == NBLOCKS - 1);
    }
    __syncthreads();

    // ---- last block: deterministic final reduction ----
    if (is_last) {
        __shared__ double dred[8];
        double s = 0.0;
        for (int i = t; i < NBLOCKS; i += 256)
            s += (double)__ldcg(&g_partial[i]);
#pragma unroll
        for (int o = 16; o; o >>= 1)
            s += __longlong_as_double(
                 __shfl_xor_sync(0xffffffffu, __double_as_longlong(s), o));
        if (lane == 0) dred[warp] = s;
        __syncthreads();
        if (t == 0) {
            double total = 0.0;
#pragma unroll
            for (int w = 0; w < 8; w++) total += dred[w];
            double score = total / ((double)BB * PCH * NN);
            out[0] = (float)(1.0 - score / (double)NN);
            g_count = 0;               // reset for next graph replay
        }
    }
}

extern "C" void kernel_launch(void* const* d_in, const int* in_sizes, int n_in,
                              void* d_out, int out_size) {
    const float* f = (const float*)d_in[0];
    const float* p = (const float*)d_in[1];
    precompute_kernel<<<(BB * NN + 63) / 64, 64>>>(f, p);
    pair_kernel<<<NBLOCKS, 256>>>(f, (float*)d_out);
}